// round 16
// baseline (speedup 1.0000x reference)
#include <cuda_runtime.h>

#define Bc 4
#define Sc 1024
#define Dc 512
#define Hc 8
#define DHc 64
#define Mt (Bc*Sc)          // 4096 rows of activations

typedef unsigned long long u64;

// ---- f32x2 packed-math helpers (FFMA2 path: ptxas only emits via PTX) ----
__device__ __forceinline__ u64 ffma2(u64 a, u64 b, u64 c) {
    u64 d;
    asm("fma.rn.f32x2 %0, %1, %2, %3;" : "=l"(d) : "l"(a), "l"(b), "l"(c));
    return d;
}
__device__ __forceinline__ u64 fmul2(u64 a, u64 b) {
    u64 d;
    asm("mul.rn.f32x2 %0, %1, %2;" : "=l"(d) : "l"(a), "l"(b));
    return d;
}
__device__ __forceinline__ u64 pack2(float lo, float hi) {
    u64 d;
    asm("mov.b64 %0, {%1, %2};" : "=l"(d)
        : "r"(__float_as_uint(lo)), "r"(__float_as_uint(hi)));
    return d;
}
__device__ __forceinline__ u64 dup2(float x) { return pack2(x, x); }
__device__ __forceinline__ float2 unpk2(u64 v) {
    unsigned lo, hi;
    asm("mov.b64 {%0, %1}, %2;" : "=r"(lo), "=r"(hi) : "l"(v));
    return make_float2(__uint_as_float(lo), __uint_as_float(hi));
}

// ---- cp.async helpers ----
__device__ __forceinline__ void cpa16(unsigned dst, const void* src) {
    asm volatile("cp.async.ca.shared.global [%0], [%1], 16;" :: "r"(dst), "l"(src));
}
__device__ __forceinline__ void cpa_commit() {
    asm volatile("cp.async.commit_group;");
}
__device__ __forceinline__ void cpa_wait0() {
    asm volatile("cp.async.wait_group 0;" ::: "memory");
}

// ---- scratch (no allocations allowed) ----
__device__ float g_Q[Bc*Hc*Sc*DHc];    // [B,H,S,DH]
__device__ float g_K[Bc*Hc*Sc*DHc];
__device__ float g_V[Bc*Hc*Sc*DHc];
__device__ float g_AT[3*Dc*Mt];        // transposed activations [3][512][4096]
__device__ float g_CT[Dc*Mt];          // transposed ctx [512][4096]
// split-K attention partials: [32 bh][8 split j-tiles][2 chunks][64 rows][68]
__device__ float g_part[32*8*2*64*68];
__device__ int   g_ctr;                // work-queue counter (reset in transpose3)

// Work-item table, rank-major (24 ranks per bh), sorted longest-first.
__constant__ signed char c_jt[24] = {15,15,14, 7,14,13,13,12, 6,12,11,11,10, 5,10, 9, 9, 8, 4, 8, 3, 2, 1, 0};
__constant__ signed char c_tb[24] = { 0, 8, 0, 0, 8, 0, 7, 0, 0, 7, 0, 6, 0, 0, 6, 0, 5, 0, 0, 5, 0, 0, 0, 0};
__constant__ signed char c_te[24] = { 8,16, 8, 8,15, 7,14, 7, 7,13, 6,12, 6, 6,11, 5,10, 5, 5, 9, 4, 3, 2, 1};
#define N_ITEMS (24*32)

// ============================================================
// Tiled transpose: in[M=4096][N=512] -> out[N=512][M=4096]
// ============================================================
__device__ __forceinline__ void transpose_body(const float* __restrict__ in,
                                               float* __restrict__ out) {
    __shared__ float t[32][33];
    const int lx = threadIdx.x & 31, ly = threadIdx.x >> 5;   // 32 x 8
    const int bx = blockIdx.x << 5;
    const int by = blockIdx.y << 5;
#pragma unroll
    for (int u = 0; u < 4; u++)
        t[ly + u*8][lx] = in[(size_t)(by + ly + u*8) * Dc + bx + lx];
    __syncthreads();
#pragma unroll
    for (int u = 0; u < 4; u++)
        out[(size_t)(bx + ly + u*8) * Mt + by + lx] = t[lx][ly + u*8];
}

__global__ __launch_bounds__(256) void transpose3(const float* __restrict__ q,
                                                  const float* __restrict__ k,
                                                  const float* __restrict__ v) {
    if (blockIdx.x == 0 && blockIdx.y == 0 && blockIdx.z == 0 && threadIdx.x == 0)
        g_ctr = 0;   // reset attn work queue (runs before attn in-stream)
    const int z = blockIdx.z;
    const float* in = (z == 0) ? q : (z == 1) ? k : v;
    transpose_body(in, g_AT + (size_t)z * Dc * Mt);
}

// ============================================================
// GEMM (cp.async pipelined): out = A[M,512] @ W[512,512],
// A supplied TRANSPOSED as AT[512][4096].
// ============================================================
__device__ __forceinline__ void gemm_ca(const float* __restrict__ AT,
                                        const float* __restrict__ W,
                                        float* __restrict__ out,
                                        int headsplit) {
    __shared__ float As[2][16][132];
    __shared__ float Bs[2][16][68];
    const int tid = threadIdx.x;
    const int tx = tid & 15;
    const int ty = tid >> 4;
    const int m0 = blockIdx.y << 7, n0 = blockIdx.x << 6;

    const int arow0 = tid >> 5;
    const int acol0 = (tid & 31) << 2;
    const int brow = tid >> 4;
    const int bcol = (tid & 15) << 2;

    const unsigned aB0 = (unsigned)__cvta_generic_to_shared(&As[0][0][0]);
    const unsigned aB1 = (unsigned)__cvta_generic_to_shared(&As[1][0][0]);
    const unsigned bB0 = (unsigned)__cvta_generic_to_shared(&Bs[0][0][0]);
    const unsigned bB1 = (unsigned)__cvta_generic_to_shared(&Bs[1][0][0]);

    const float* Abase = AT + m0 + (size_t)arow0 * Mt + acol0;
    const float* Wbase = W + n0 + (size_t)brow * Dc + bcol;

    u64 acc[4][4];
#pragma unroll
    for (int i = 0; i < 4; i++)
#pragma unroll
        for (int j = 0; j < 4; j++) acc[i][j] = 0ull;

    auto issue = [&](int buf, int k0) {
        const unsigned aB = buf ? aB1 : aB0;
        const unsigned bB = buf ? bB1 : bB0;
        cpa16(aB + (unsigned)(arow0 * 132 + acol0) * 4,
              Abase + (size_t)k0 * Mt);
        cpa16(aB + (unsigned)((arow0 + 8) * 132 + acol0) * 4,
              Abase + (size_t)(k0 + 8) * Mt);
        cpa16(bB + (unsigned)(brow * 68 + bcol) * 4,
              Wbase + (size_t)k0 * Dc);
    };

    issue(0, 0);
    cpa_commit();

    int buf = 0;
#pragma unroll 1
    for (int k0 = 0; k0 < 512; k0 += 16) {
        cpa_wait0();
        __syncthreads();
        if (k0 + 16 < 512) {
            issue(buf ^ 1, k0 + 16);
            cpa_commit();
        }
#pragma unroll
        for (int kk = 0; kk < 16; kk++) {
            ulonglong2 a01 = *(ulonglong2*)&As[buf][kk][ty*8];
            ulonglong2 a23 = *(ulonglong2*)&As[buf][kk][ty*8 + 4];
            float4 bv = *(float4*)&Bs[buf][kk][tx*4];
            u64 a2[4] = { a01.x, a01.y, a23.x, a23.y };
            u64 b2[4] = { dup2(bv.x), dup2(bv.y), dup2(bv.z), dup2(bv.w) };
#pragma unroll
            for (int i = 0; i < 4; i++)
#pragma unroll
                for (int j = 0; j < 4; j++)
                    acc[i][j] = ffma2(a2[i], b2[j], acc[i][j]);
        }
        buf ^= 1;
    }

    const int n = n0 + tx*4;
    if (headsplit) {
        const int hh = n >> 6;
        const int nc = n & 63;
#pragma unroll
        for (int i = 0; i < 4; i++) {
            float2 c0 = unpk2(acc[i][0]), c1 = unpk2(acc[i][1]);
            float2 c2 = unpk2(acc[i][2]), c3 = unpk2(acc[i][3]);
            int m = m0 + ty*8 + 2*i;
            int bb = m >> 10, s = m & 1023;
            *(float4*)&out[((size_t)(bb*Hc + hh) * Sc + s) * DHc + nc] =
                make_float4(c0.x, c1.x, c2.x, c3.x);
            int m2 = m + 1, bb2 = m2 >> 10, s2 = m2 & 1023;
            *(float4*)&out[((size_t)(bb2*Hc + hh) * Sc + s2) * DHc + nc] =
                make_float4(c0.y, c1.y, c2.y, c3.y);
        }
    } else {
#pragma unroll
        for (int i = 0; i < 4; i++) {
            float2 c0 = unpk2(acc[i][0]), c1 = unpk2(acc[i][1]);
            float2 c2 = unpk2(acc[i][2]), c3 = unpk2(acc[i][3]);
            int m = m0 + ty*8 + 2*i;
            *(float4*)&out[(size_t)m * 512 + n] = make_float4(c0.x, c1.x, c2.x, c3.x);
            *(float4*)&out[(size_t)(m+1) * 512 + n] = make_float4(c0.y, c1.y, c2.y, c3.y);
        }
    }
}

__global__ __launch_bounds__(256, 3) void proj3(const float* __restrict__ W0,
                                                const float* __restrict__ W1,
                                                const float* __restrict__ W2,
                                                float* __restrict__ O0,
                                                float* __restrict__ O1,
                                                float* __restrict__ O2) {
    const int z = blockIdx.z;
    const float* AT = g_AT + (size_t)z * Dc * Mt;
    const float* W = (z == 0) ? W0 : (z == 1) ? W1 : W2;
    float*       O = (z == 0) ? O0 : (z == 1) ? O1 : O2;
    gemm_ca(AT, W, O, 1);
}

__global__ __launch_bounds__(256, 3) void gemm_out(const float* __restrict__ W,
                                                   float* __restrict__ out) {
    gemm_ca(g_CT, W, out, 0);
}

// ============================================================
// Persistent work-stealing attention (LPT order). Split j-tiles
// (jt>=8) write unnormalized partials; singles write the
// TRANSPOSED ctx g_CT directly (no transpose kernel needed).
// R and V tile loads via cp.async.
// ============================================================
__global__ __launch_bounds__(256, 3) void attn_kernel(const float* __restrict__ Rel) {
    extern __shared__ float sm[];
    float* qs = sm;                 // [d][j]  64x68
    float* kv = qs + 64*68;         // QK: K as [d][t] ; PV: V as [t][d]
    float* rp = kv + 64*68;         // QK: R as [d][cc] 64x128 ; PV: ps as [t][j]
    int*   sm_item = (int*)(rp + 64*128);   // 1-int broadcast slot

    const unsigned kvS = (unsigned)__cvta_generic_to_shared(kv);
    const unsigned rpS = (unsigned)__cvta_generic_to_shared(rp);

    const int tid = threadIdx.x;
    const int tx = tid & 15, ty = tid >> 4;
    const int base0 = 60 + 4*tx - 4*ty;   // in [0,120], mult of 4

    for (;;) {
        __syncthreads();              // prior item fully done; slot reusable
        if (tid == 0) *sm_item = atomicAdd(&g_ctr, 1);
        __syncthreads();
        const int item = *sm_item;
        if (item >= N_ITEMS) break;

        const int bh   = item & 31;
        const int rank = item >> 5;
        const int jt   = c_jt[rank];
        const int tbeg = c_tb[rank], tend = c_te[rank];
        const bool split = (jt >= 8);
        const int ci   = tbeg ? 1 : 0;
        const int j0   = jt << 6;
        const int h    = bh & (Hc-1);

        const float* Qp    = g_Q + ((size_t)bh * Sc + j0) * DHc;
        const float* Kbase = g_K + (size_t)bh * Sc * DHc;
        const float* Vbase = g_V + (size_t)bh * Sc * DHc;
        const float* Rp    = Rel + (size_t)h * DHc * Sc;

        for (int f = tid; f < 1024; f += 256) {
            int j = f >> 4, d4 = (f & 15) << 2;
            float4 v = *(const float4*)(Qp + j*DHc + d4);
            qs[(d4+0)*68 + j] = v.x; qs[(d4+1)*68 + j] = v.y;
            qs[(d4+2)*68 + j] = v.z; qs[(d4+3)*68 + j] = v.w;
        }

        float mrow[4] = {-1e30f, -1e30f, -1e30f, -1e30f};
        float lrow[4] = {0.f, 0.f, 0.f, 0.f};
        u64 oacc2[4][2];
#pragma unroll
        for (int i = 0; i < 4; i++) { oacc2[i][0] = 0ull; oacc2[i][1] = 0ull; }

        for (int it = tbeg; it < tend; it++) {
            const int t0 = it << 6;
            __syncthreads();   // (a) qs visible; kv/rp free

            // R window via cp.async (zero-fill OOB chunks with STS)
            const int cmin = Sc - 64 - j0 + t0;   // >= 0, multiple of 4
            for (int f = tid; f < 64*32; f += 256) {
                int d = f >> 5, cc4 = (f & 31) << 2;
                int col = cmin + cc4;
                if (col < Sc)
                    cpa16(rpS + (unsigned)(d*128 + cc4) * 4,
                          Rp + (size_t)d*Sc + col);
                else
                    *(float4*)(rp + d*128 + cc4) = make_float4(0.f, 0.f, 0.f, 0.f);
            }
            cpa_commit();
            // K tile (transposed store; stays LDG+STS)
            for (int f = tid; f < 1024; f += 256) {
                int t = f >> 4, d4 = (f & 15) << 2;
                float4 k4 = *(const float4*)(Kbase + (size_t)(t0 + t)*DHc + d4);
                kv[(d4+0)*68 + t] = k4.x; kv[(d4+1)*68 + t] = k4.y;
                kv[(d4+2)*68 + t] = k4.z; kv[(d4+3)*68 + t] = k4.w;
            }
            cpa_wait0();
            __syncthreads();   // (b)

            // s[j][t] = q.k + q.R[:, S-1-j+t]  -- f32x2, pairs along t
            u64 acc2[4][2];
#pragma unroll
            for (int i = 0; i < 4; i++) { acc2[i][0] = 0ull; acc2[i][1] = 0ull; }
#pragma unroll 8
            for (int d = 0; d < 64; d++) {
                float4 qv = *(float4*)(qs + d*68 + ty*4);
                ulonglong2 kk2 = *(ulonglong2*)(kv + d*68 + tx*4);
                const float* rrow = rp + d*128 + base0;
                u64 e0 = *(const u64*)(rrow);       // {f0,f1}  (8B aligned)
                u64 e1 = *(const u64*)(rrow + 2);   // {f2,f3}
                u64 e2 = *(const u64*)(rrow + 4);   // {f4,f5}
                float f6 = rrow[6];
                float2 E0 = unpk2(e0), E1 = unpk2(e1), E2 = unpk2(e2);
                u64 o1 = pack2(E0.y, E1.x);
                u64 o3 = pack2(E1.y, E2.x);
                u64 o5 = pack2(E2.y, f6);
                u64 qa2[4] = { dup2(qv.x), dup2(qv.y), dup2(qv.z), dup2(qv.w) };
                u64 rb00 = o3, rb01 = o5;   // i=0
                u64 rb10 = e1, rb11 = e2;   // i=1
                u64 rb20 = o1, rb21 = o3;   // i=2
                u64 rb30 = e0, rb31 = e1;   // i=3
                acc2[0][0] = ffma2(qa2[0], kk2.x, acc2[0][0]);
                acc2[0][1] = ffma2(qa2[0], kk2.y, acc2[0][1]);
                acc2[0][0] = ffma2(qa2[0], rb00,  acc2[0][0]);
                acc2[0][1] = ffma2(qa2[0], rb01,  acc2[0][1]);
                acc2[1][0] = ffma2(qa2[1], kk2.x, acc2[1][0]);
                acc2[1][1] = ffma2(qa2[1], kk2.y, acc2[1][1]);
                acc2[1][0] = ffma2(qa2[1], rb10,  acc2[1][0]);
                acc2[1][1] = ffma2(qa2[1], rb11,  acc2[1][1]);
                acc2[2][0] = ffma2(qa2[2], kk2.x, acc2[2][0]);
                acc2[2][1] = ffma2(qa2[2], kk2.y, acc2[2][1]);
                acc2[2][0] = ffma2(qa2[2], rb20,  acc2[2][0]);
                acc2[2][1] = ffma2(qa2[2], rb21,  acc2[2][1]);
                acc2[3][0] = ffma2(qa2[3], kk2.x, acc2[3][0]);
                acc2[3][1] = ffma2(qa2[3], kk2.y, acc2[3][1]);
                acc2[3][0] = ffma2(qa2[3], rb30,  acc2[3][0]);
                acc2[3][1] = ffma2(qa2[3], rb31,  acc2[3][1]);
            }

            float acc[4][4];
#pragma unroll
            for (int i = 0; i < 4; i++) {
                float2 u0 = unpk2(acc2[i][0]), u1 = unpk2(acc2[i][1]);
                acc[i][0] = u0.x; acc[i][1] = u0.y; acc[i][2] = u1.x; acc[i][3] = u1.y;
            }

            // online softmax (scale AFTER bias+mask, matching reference)
#pragma unroll
            for (int i = 0; i < 4; i++) {
                const int j = j0 + ty*4 + i;
                float mx = -1e30f;
#pragma unroll
                for (int c = 0; c < 4; c++) {
                    int t = t0 + tx*4 + c;
                    float v = (t <= j) ? acc[i][c] * 0.125f : -1e30f;
                    acc[i][c] = v;
                    mx = fmaxf(mx, v);
                }
#pragma unroll
                for (int off = 8; off; off >>= 1)
                    mx = fmaxf(mx, __shfl_xor_sync(0xffffffffu, mx, off, 16));
                float mnew = fmaxf(mrow[i], mx);
                float corr = __expf(mrow[i] - mnew);
                float ss = 0.f;
#pragma unroll
                for (int c = 0; c < 4; c++) {
                    float p = __expf(acc[i][c] - mnew);
                    acc[i][c] = p;
                    ss += p;
                }
#pragma unroll
                for (int off = 8; off; off >>= 1)
                    ss += __shfl_xor_sync(0xffffffffu, ss, off, 16);
                lrow[i] = lrow[i] * corr + ss;
                mrow[i] = mnew;
                u64 corr2 = dup2(corr);
                oacc2[i][0] = fmul2(oacc2[i][0], corr2);
                oacc2[i][1] = fmul2(oacc2[i][1], corr2);
            }
            __syncthreads();   // (c)

            // V tile via cp.async -> kv[t][d]; p transposed -> ps[t][j] in rp
            for (int f = tid; f < 1024; f += 256) {
                int t = f >> 4, d4 = (f & 15) << 2;
                cpa16(kvS + (unsigned)(t*68 + d4) * 4,
                      Vbase + (size_t)(t0 + t)*DHc + d4);
            }
            cpa_commit();
            float* ps = rp;
#pragma unroll
            for (int c = 0; c < 4; c++) {
                float4 pv = make_float4(acc[0][c], acc[1][c], acc[2][c], acc[3][c]);
                *(float4*)(ps + (tx*4 + c)*68 + ty*4) = pv;
            }
            cpa_wait0();
            __syncthreads();   // (d)

            // O += P @ V  (f32x2, pairs along DH cols)
#pragma unroll 8
            for (int t = 0; t < 64; t++) {
                ulonglong2 vv2 = *(ulonglong2*)(kv + t*68 + tx*4);
                float4 p4 = *(float4*)(ps + t*68 + ty*4);
                u64 pa0 = dup2(p4.x), pa1 = dup2(p4.y), pa2v = dup2(p4.z), pa3 = dup2(p4.w);
                oacc2[0][0] = ffma2(pa0,  vv2.x, oacc2[0][0]);
                oacc2[0][1] = ffma2(pa0,  vv2.y, oacc2[0][1]);
                oacc2[1][0] = ffma2(pa1,  vv2.x, oacc2[1][0]);
                oacc2[1][1] = ffma2(pa1,  vv2.y, oacc2[1][1]);
                oacc2[2][0] = ffma2(pa2v, vv2.x, oacc2[2][0]);
                oacc2[2][1] = ffma2(pa2v, vv2.y, oacc2[2][1]);
                oacc2[3][0] = ffma2(pa3,  vv2.x, oacc2[3][0]);
                oacc2[3][1] = ffma2(pa3,  vv2.y, oacc2[3][1]);
            }
        }

        if (!split) {
            // direct TRANSPOSED epilogue: g_CT[h*64+dc][b*1024 + j]
            const int b = bh >> 3;
            float o[4][4];
#pragma unroll
            for (int i = 0; i < 4; i++) {
                float inv = 1.f / lrow[i];
                float2 u0 = unpk2(oacc2[i][0]), u1 = unpk2(oacc2[i][1]);
                o[i][0] = u0.x*inv; o[i][1] = u0.y*inv;
                o[i][2] = u1.x*inv; o[i][3] = u1.y*inv;
            }
#pragma unroll
            for (int c = 0; c < 4; c++) {
                float4 v = make_float4(o[0][c], o[1][c], o[2][c], o[3][c]);
                *(float4*)&g_CT[(size_t)(h*DHc + tx*4 + c) * Mt + b*Sc + j0 + ty*4] = v;
            }
        } else {
            float* P = g_part + (size_t)(((bh*8 + (jt - 8)) << 1) + ci) * 64 * 68;
#pragma unroll
            for (int i = 0; i < 4; i++) {
                const int r = ty*4 + i;
                float2 u0 = unpk2(oacc2[i][0]), u1 = unpk2(oacc2[i][1]);
                *(float4*)&P[r*68 + tx*4] = make_float4(u0.x, u0.y, u1.x, u1.y);
                if (tx == 0) {
                    P[r*68 + 64] = mrow[i];
                    P[r*68 + 65] = lrow[i];
                }
            }
        }
    }
}

// ============================================================
// Combine split-K partials straight into g_CT (transposed).
// One CTA per (bh, split j-tile); thread -> (dc-row, j-range).
// ============================================================
__global__ __launch_bounds__(256) void attn_combine() {
    __shared__ float sfA[64], sfB[64];
    const int bh = blockIdx.x >> 3;
    const int jt = 8 + (blockIdx.x & 7);
    const int j0 = jt << 6;
    const int b = bh >> 3, h = bh & 7;

    const float* PA = g_part + (size_t)(((bh*8 + (jt - 8)) << 1) + 0) * 64 * 68;
    const float* PB = g_part + (size_t)(((bh*8 + (jt - 8)) << 1) + 1) * 64 * 68;

    if (threadIdx.x < 64) {
        const int r = threadIdx.x;
        const float mA = PA[r*68 + 64], lA = PA[r*68 + 65];
        const float mB = PB[r*68 + 64], lB = PB[r*68 + 65];
        const float m  = fmaxf(mA, mB);
        const float wA = __expf(mA - m), wB = __expf(mB - m);
        const float inv = 1.f / (wA*lA + wB*lB);
        sfA[r] = wA * inv; sfB[r] = wB * inv;
    }
    __syncthreads();

    const int c  = threadIdx.x & 63;      // dc row of g_CT
    const int jg = threadIdx.x >> 6;      // 0..3 (16 j each)

    float buf[16];
#pragma unroll
    for (int u = 0; u < 16; u++) {
        const int r = jg*16 + u;
        buf[u] = sfA[r] * PA[r*68 + c] + sfB[r] * PB[r*68 + c];
    }
    float* dst = &g_CT[(size_t)(h*DHc + c) * Mt + b*Sc + j0 + jg*16];
#pragma unroll
    for (int u = 0; u < 16; u += 4)
        *(float4*)&dst[u] = make_float4(buf[u], buf[u+1], buf[u+2], buf[u+3]);
}

// ============================================================
extern "C" void kernel_launch(void* const* d_in, const int* in_sizes, int n_in,
                              void* d_out, int out_size) {
    (void)in_sizes; (void)n_in; (void)out_size;
    const float* queries = (const float*)d_in[0];
    const float* keysp   = (const float*)d_in[1];
    const float* valuesp = (const float*)d_in[2];
    // d_in[3] = mask (causal; applied analytically)
    const float* Wq  = (const float*)d_in[4];
    const float* Wk  = (const float*)d_in[5];
    const float* Wv  = (const float*)d_in[6];
    const float* Wo  = (const float*)d_in[7];
    const float* rel = (const float*)d_in[8];
    float* out = (float*)d_out;

    float *pQ, *pK, *pV;
    cudaGetSymbolAddress((void**)&pQ, g_Q);
    cudaGetSymbolAddress((void**)&pK, g_K);
    cudaGetSymbolAddress((void**)&pV, g_V);

    // 1) transpose activations -> g_AT (also resets attn work queue)
    transpose3<<<dim3(Dc/32, Mt/32, 3), 256>>>(queries, keysp, valuesp);

    // 2) fused QKV projections (cp.async pipelined GEMM)
    proj3<<<dim3(Dc/64, Mt/128, 3), 256>>>(Wq, Wk, Wv, pQ, pK, pV);

    // 3) attention: persistent work-stealing workers (152 SM * 3)
    const int smem = (2*64*68 + 64*128 + 4) * (int)sizeof(float);
    cudaFuncSetAttribute(attn_kernel, cudaFuncAttributeMaxDynamicSharedMemorySize, smem);
    attn_kernel<<<456, 256, smem>>>(rel);

    // 3b) merge partials for split j-tiles -> g_CT
    attn_combine<<<Bc*Hc*8, 256>>>();

    // 4) output projection reads g_CT directly (transpose1 eliminated)
    gemm_out<<<dim3(Dc/64, Mt/128), 256>>>(Wo, out);
}

// round 17
// speedup vs baseline: 1.0657x; 1.0657x over previous
#include <cuda_runtime.h>

#define Bc 4
#define Sc 1024
#define Dc 512
#define Hc 8
#define DHc 64
#define Mt (Bc*Sc)          // 4096 rows of activations

typedef unsigned long long u64;

// ---- f32x2 packed-math helpers (FFMA2 path: ptxas only emits via PTX) ----
__device__ __forceinline__ u64 ffma2(u64 a, u64 b, u64 c) {
    u64 d;
    asm("fma.rn.f32x2 %0, %1, %2, %3;" : "=l"(d) : "l"(a), "l"(b), "l"(c));
    return d;
}
__device__ __forceinline__ u64 fmul2(u64 a, u64 b) {
    u64 d;
    asm("mul.rn.f32x2 %0, %1, %2;" : "=l"(d) : "l"(a), "l"(b));
    return d;
}
__device__ __forceinline__ u64 pack2(float lo, float hi) {
    u64 d;
    asm("mov.b64 %0, {%1, %2};" : "=l"(d)
        : "r"(__float_as_uint(lo)), "r"(__float_as_uint(hi)));
    return d;
}
__device__ __forceinline__ u64 dup2(float x) { return pack2(x, x); }
__device__ __forceinline__ float2 unpk2(u64 v) {
    unsigned lo, hi;
    asm("mov.b64 {%0, %1}, %2;" : "=r"(lo), "=r"(hi) : "l"(v));
    return make_float2(__uint_as_float(lo), __uint_as_float(hi));
}

// ---- cp.async helpers ----
__device__ __forceinline__ void cpa16(unsigned dst, const void* src) {
    asm volatile("cp.async.ca.shared.global [%0], [%1], 16;" :: "r"(dst), "l"(src));
}
__device__ __forceinline__ void cpa_commit() {
    asm volatile("cp.async.commit_group;");
}
__device__ __forceinline__ void cpa_wait0() {
    asm volatile("cp.async.wait_group 0;" ::: "memory");
}

// ---- scratch (no allocations allowed) ----
__device__ float g_Q[Bc*Hc*Sc*DHc];    // [B,H,S,DH]
__device__ float g_K[Bc*Hc*Sc*DHc];
__device__ float g_V[Bc*Hc*Sc*DHc];
__device__ float g_AT[3*Dc*Mt];        // transposed activations [3][512][4096]
__device__ float g_CT[Dc*Mt];          // transposed ctx [512][4096]
// split-K attention partials: [32 bh][8 split j-tiles][2 chunks][64 rows][68]
__device__ float g_part[32*8*2*64*68];
__device__ int   g_ctr;                // work-queue counter (reset in transpose3)

// Work-item table, rank-major (24 ranks per bh), sorted longest-first.
__constant__ signed char c_jt[24] = {15,15,14, 7,14,13,13,12, 6,12,11,11,10, 5,10, 9, 9, 8, 4, 8, 3, 2, 1, 0};
__constant__ signed char c_tb[24] = { 0, 8, 0, 0, 8, 0, 7, 0, 0, 7, 0, 6, 0, 0, 6, 0, 5, 0, 0, 5, 0, 0, 0, 0};
__constant__ signed char c_te[24] = { 8,16, 8, 8,15, 7,14, 7, 7,13, 6,12, 6, 6,11, 5,10, 5, 5, 9, 4, 3, 2, 1};
#define N_ITEMS (24*32)

// ============================================================
// Tiled transpose: in[M=4096][N=512] -> out[N=512][M=4096]
// ============================================================
__device__ __forceinline__ void transpose_body(const float* __restrict__ in,
                                               float* __restrict__ out) {
    __shared__ float t[32][33];
    const int lx = threadIdx.x & 31, ly = threadIdx.x >> 5;   // 32 x 8
    const int bx = blockIdx.x << 5;
    const int by = blockIdx.y << 5;
#pragma unroll
    for (int u = 0; u < 4; u++)
        t[ly + u*8][lx] = in[(size_t)(by + ly + u*8) * Dc + bx + lx];
    __syncthreads();
#pragma unroll
    for (int u = 0; u < 4; u++)
        out[(size_t)(bx + ly + u*8) * Mt + by + lx] = t[lx][ly + u*8];
}

__global__ __launch_bounds__(256) void transpose3(const float* __restrict__ q,
                                                  const float* __restrict__ k,
                                                  const float* __restrict__ v) {
    if (blockIdx.x == 0 && blockIdx.y == 0 && blockIdx.z == 0 && threadIdx.x == 0)
        g_ctr = 0;   // reset attn work queue (runs before attn in-stream)
    const int z = blockIdx.z;
    const float* in = (z == 0) ? q : (z == 1) ? k : v;
    transpose_body(in, g_AT + (size_t)z * Dc * Mt);
}

// ============================================================
// GEMM (cp.async pipelined): out = A[M,512] @ W[512,512],
// A supplied TRANSPOSED as AT[512][4096].
// ============================================================
__device__ __forceinline__ void gemm_ca(const float* __restrict__ AT,
                                        const float* __restrict__ W,
                                        float* __restrict__ out,
                                        int headsplit) {
    __shared__ float As[2][16][132];
    __shared__ float Bs[2][16][68];
    const int tid = threadIdx.x;
    const int tx = tid & 15;
    const int ty = tid >> 4;
    const int m0 = blockIdx.y << 7, n0 = blockIdx.x << 6;

    const int arow0 = tid >> 5;
    const int acol0 = (tid & 31) << 2;
    const int brow = tid >> 4;
    const int bcol = (tid & 15) << 2;

    const unsigned aB0 = (unsigned)__cvta_generic_to_shared(&As[0][0][0]);
    const unsigned aB1 = (unsigned)__cvta_generic_to_shared(&As[1][0][0]);
    const unsigned bB0 = (unsigned)__cvta_generic_to_shared(&Bs[0][0][0]);
    const unsigned bB1 = (unsigned)__cvta_generic_to_shared(&Bs[1][0][0]);

    const float* Abase = AT + m0 + (size_t)arow0 * Mt + acol0;
    const float* Wbase = W + n0 + (size_t)brow * Dc + bcol;

    u64 acc[4][4];
#pragma unroll
    for (int i = 0; i < 4; i++)
#pragma unroll
        for (int j = 0; j < 4; j++) acc[i][j] = 0ull;

    auto issue = [&](int buf, int k0) {
        const unsigned aB = buf ? aB1 : aB0;
        const unsigned bB = buf ? bB1 : bB0;
        cpa16(aB + (unsigned)(arow0 * 132 + acol0) * 4,
              Abase + (size_t)k0 * Mt);
        cpa16(aB + (unsigned)((arow0 + 8) * 132 + acol0) * 4,
              Abase + (size_t)(k0 + 8) * Mt);
        cpa16(bB + (unsigned)(brow * 68 + bcol) * 4,
              Wbase + (size_t)k0 * Dc);
    };

    issue(0, 0);
    cpa_commit();

    int buf = 0;
#pragma unroll 1
    for (int k0 = 0; k0 < 512; k0 += 16) {
        cpa_wait0();
        __syncthreads();
        if (k0 + 16 < 512) {
            issue(buf ^ 1, k0 + 16);
            cpa_commit();
        }
#pragma unroll
        for (int kk = 0; kk < 16; kk++) {
            ulonglong2 a01 = *(ulonglong2*)&As[buf][kk][ty*8];
            ulonglong2 a23 = *(ulonglong2*)&As[buf][kk][ty*8 + 4];
            float4 bv = *(float4*)&Bs[buf][kk][tx*4];
            u64 a2[4] = { a01.x, a01.y, a23.x, a23.y };
            u64 b2[4] = { dup2(bv.x), dup2(bv.y), dup2(bv.z), dup2(bv.w) };
#pragma unroll
            for (int i = 0; i < 4; i++)
#pragma unroll
                for (int j = 0; j < 4; j++)
                    acc[i][j] = ffma2(a2[i], b2[j], acc[i][j]);
        }
        buf ^= 1;
    }

    const int n = n0 + tx*4;
    if (headsplit) {
        const int hh = n >> 6;
        const int nc = n & 63;
#pragma unroll
        for (int i = 0; i < 4; i++) {
            float2 c0 = unpk2(acc[i][0]), c1 = unpk2(acc[i][1]);
            float2 c2 = unpk2(acc[i][2]), c3 = unpk2(acc[i][3]);
            int m = m0 + ty*8 + 2*i;
            int bb = m >> 10, s = m & 1023;
            *(float4*)&out[((size_t)(bb*Hc + hh) * Sc + s) * DHc + nc] =
                make_float4(c0.x, c1.x, c2.x, c3.x);
            int m2 = m + 1, bb2 = m2 >> 10, s2 = m2 & 1023;
            *(float4*)&out[((size_t)(bb2*Hc + hh) * Sc + s2) * DHc + nc] =
                make_float4(c0.y, c1.y, c2.y, c3.y);
        }
    } else {
#pragma unroll
        for (int i = 0; i < 4; i++) {
            float2 c0 = unpk2(acc[i][0]), c1 = unpk2(acc[i][1]);
            float2 c2 = unpk2(acc[i][2]), c3 = unpk2(acc[i][3]);
            int m = m0 + ty*8 + 2*i;
            *(float4*)&out[(size_t)m * 512 + n] = make_float4(c0.x, c1.x, c2.x, c3.x);
            *(float4*)&out[(size_t)(m+1) * 512 + n] = make_float4(c0.y, c1.y, c2.y, c3.y);
        }
    }
}

__global__ __launch_bounds__(256, 3) void proj3(const float* __restrict__ W0,
                                                const float* __restrict__ W1,
                                                const float* __restrict__ W2,
                                                float* __restrict__ O0,
                                                float* __restrict__ O1,
                                                float* __restrict__ O2) {
    const int z = blockIdx.z;
    const float* AT = g_AT + (size_t)z * Dc * Mt;
    const float* W = (z == 0) ? W0 : (z == 1) ? W1 : W2;
    float*       O = (z == 0) ? O0 : (z == 1) ? O1 : O2;
    gemm_ca(AT, W, O, 1);
}

__global__ __launch_bounds__(256, 3) void gemm_out(const float* __restrict__ W,
                                                   float* __restrict__ out) {
    gemm_ca(g_CT, W, out, 0);
}

// ============================================================
// Persistent work-stealing attention (LPT order). Split j-tiles
// (jt>=8) write unnormalized partials; singles write the
// TRANSPOSED ctx g_CT directly. R and V tile loads via cp.async.
// QK inner loop: R15-proven LDS.128 form (conflict-free).
// ============================================================
__global__ __launch_bounds__(256, 3) void attn_kernel(const float* __restrict__ Rel) {
    extern __shared__ float sm[];
    float* qs = sm;                 // [d][j]  64x68
    float* kv = qs + 64*68;         // QK: K as [d][t] ; PV: V as [t][d]
    float* rp = kv + 64*68;         // QK: R as [d][cc] 64x128 ; PV: ps as [t][j]
    int*   sm_item = (int*)(rp + 64*128);   // 1-int broadcast slot

    const unsigned kvS = (unsigned)__cvta_generic_to_shared(kv);
    const unsigned rpS = (unsigned)__cvta_generic_to_shared(rp);

    const int tid = threadIdx.x;
    const int tx = tid & 15, ty = tid >> 4;
    const int base0 = 60 + 4*tx - 4*ty;   // in [0,120], mult of 4

    for (;;) {
        __syncthreads();              // prior item fully done; slot reusable
        if (tid == 0) *sm_item = atomicAdd(&g_ctr, 1);
        __syncthreads();
        const int item = *sm_item;
        if (item >= N_ITEMS) break;

        const int bh   = item & 31;
        const int rank = item >> 5;
        const int jt   = c_jt[rank];
        const int tbeg = c_tb[rank], tend = c_te[rank];
        const bool split = (jt >= 8);
        const int ci   = tbeg ? 1 : 0;
        const int j0   = jt << 6;
        const int h    = bh & (Hc-1);

        const float* Qp    = g_Q + ((size_t)bh * Sc + j0) * DHc;
        const float* Kbase = g_K + (size_t)bh * Sc * DHc;
        const float* Vbase = g_V + (size_t)bh * Sc * DHc;
        const float* Rp    = Rel + (size_t)h * DHc * Sc;

        for (int f = tid; f < 1024; f += 256) {
            int j = f >> 4, d4 = (f & 15) << 2;
            float4 v = *(const float4*)(Qp + j*DHc + d4);
            qs[(d4+0)*68 + j] = v.x; qs[(d4+1)*68 + j] = v.y;
            qs[(d4+2)*68 + j] = v.z; qs[(d4+3)*68 + j] = v.w;
        }

        float mrow[4] = {-1e30f, -1e30f, -1e30f, -1e30f};
        float lrow[4] = {0.f, 0.f, 0.f, 0.f};
        u64 oacc2[4][2];
#pragma unroll
        for (int i = 0; i < 4; i++) { oacc2[i][0] = 0ull; oacc2[i][1] = 0ull; }

        for (int it = tbeg; it < tend; it++) {
            const int t0 = it << 6;
            __syncthreads();   // (a) qs visible; kv/rp free

            // R window via cp.async (zero-fill OOB chunks with STS)
            const int cmin = Sc - 64 - j0 + t0;   // >= 0, multiple of 4
            for (int f = tid; f < 64*32; f += 256) {
                int d = f >> 5, cc4 = (f & 31) << 2;
                int col = cmin + cc4;
                if (col < Sc)
                    cpa16(rpS + (unsigned)(d*128 + cc4) * 4,
                          Rp + (size_t)d*Sc + col);
                else
                    *(float4*)(rp + d*128 + cc4) = make_float4(0.f, 0.f, 0.f, 0.f);
            }
            cpa_commit();
            // K tile (transposed store; stays LDG+STS)
            for (int f = tid; f < 1024; f += 256) {
                int t = f >> 4, d4 = (f & 15) << 2;
                float4 k4 = *(const float4*)(Kbase + (size_t)(t0 + t)*DHc + d4);
                kv[(d4+0)*68 + t] = k4.x; kv[(d4+1)*68 + t] = k4.y;
                kv[(d4+2)*68 + t] = k4.z; kv[(d4+3)*68 + t] = k4.w;
            }
            cpa_wait0();
            __syncthreads();   // (b)

            // s[j][t] = q.k + q.R[:, S-1-j+t]  -- f32x2, pairs along t
            // (R15-proven: two conflict-free LDS.128 R loads + 6 packs)
            u64 acc2[4][2];
#pragma unroll
            for (int i = 0; i < 4; i++) { acc2[i][0] = 0ull; acc2[i][1] = 0ull; }
#pragma unroll 8
            for (int d = 0; d < 64; d++) {
                float4 qv = *(float4*)(qs + d*68 + ty*4);
                ulonglong2 kk2 = *(ulonglong2*)(kv + d*68 + tx*4);
                float4 r0 = *(float4*)(rp + d*128 + base0);
                float4 r1 = *(float4*)(rp + d*128 + base0 + 4);
                u64 qa2[4] = { dup2(qv.x), dup2(qv.y), dup2(qv.z), dup2(qv.w) };
                u64 e0 = pack2(r0.x, r0.y), e1 = pack2(r0.z, r0.w), e2 = pack2(r1.x, r1.y);
                u64 o1 = pack2(r0.y, r0.z), o3 = pack2(r0.w, r1.x), o5 = pack2(r1.y, r1.z);
                u64 rb00 = o3, rb01 = o5;   // i=0
                u64 rb10 = e1, rb11 = e2;   // i=1
                u64 rb20 = o1, rb21 = o3;   // i=2
                u64 rb30 = e0, rb31 = e1;   // i=3
                acc2[0][0] = ffma2(qa2[0], kk2.x, acc2[0][0]);
                acc2[0][1] = ffma2(qa2[0], kk2.y, acc2[0][1]);
                acc2[0][0] = ffma2(qa2[0], rb00,  acc2[0][0]);
                acc2[0][1] = ffma2(qa2[0], rb01,  acc2[0][1]);
                acc2[1][0] = ffma2(qa2[1], kk2.x, acc2[1][0]);
                acc2[1][1] = ffma2(qa2[1], kk2.y, acc2[1][1]);
                acc2[1][0] = ffma2(qa2[1], rb10,  acc2[1][0]);
                acc2[1][1] = ffma2(qa2[1], rb11,  acc2[1][1]);
                acc2[2][0] = ffma2(qa2[2], kk2.x, acc2[2][0]);
                acc2[2][1] = ffma2(qa2[2], kk2.y, acc2[2][1]);
                acc2[2][0] = ffma2(qa2[2], rb20,  acc2[2][0]);
                acc2[2][1] = ffma2(qa2[2], rb21,  acc2[2][1]);
                acc2[3][0] = ffma2(qa2[3], kk2.x, acc2[3][0]);
                acc2[3][1] = ffma2(qa2[3], kk2.y, acc2[3][1]);
                acc2[3][0] = ffma2(qa2[3], rb30,  acc2[3][0]);
                acc2[3][1] = ffma2(qa2[3], rb31,  acc2[3][1]);
            }

            float acc[4][4];
#pragma unroll
            for (int i = 0; i < 4; i++) {
                float2 u0 = unpk2(acc2[i][0]), u1 = unpk2(acc2[i][1]);
                acc[i][0] = u0.x; acc[i][1] = u0.y; acc[i][2] = u1.x; acc[i][3] = u1.y;
            }

            // online softmax (scale AFTER bias+mask, matching reference)
#pragma unroll
            for (int i = 0; i < 4; i++) {
                const int j = j0 + ty*4 + i;
                float mx = -1e30f;
#pragma unroll
                for (int c = 0; c < 4; c++) {
                    int t = t0 + tx*4 + c;
                    float v = (t <= j) ? acc[i][c] * 0.125f : -1e30f;
                    acc[i][c] = v;
                    mx = fmaxf(mx, v);
                }
#pragma unroll
                for (int off = 8; off; off >>= 1)
                    mx = fmaxf(mx, __shfl_xor_sync(0xffffffffu, mx, off, 16));
                float mnew = fmaxf(mrow[i], mx);
                float corr = __expf(mrow[i] - mnew);
                float ss = 0.f;
#pragma unroll
                for (int c = 0; c < 4; c++) {
                    float p = __expf(acc[i][c] - mnew);
                    acc[i][c] = p;
                    ss += p;
                }
#pragma unroll
                for (int off = 8; off; off >>= 1)
                    ss += __shfl_xor_sync(0xffffffffu, ss, off, 16);
                lrow[i] = lrow[i] * corr + ss;
                mrow[i] = mnew;
                u64 corr2 = dup2(corr);
                oacc2[i][0] = fmul2(oacc2[i][0], corr2);
                oacc2[i][1] = fmul2(oacc2[i][1], corr2);
            }
            __syncthreads();   // (c)

            // V tile via cp.async -> kv[t][d]; p transposed -> ps[t][j] in rp
            for (int f = tid; f < 1024; f += 256) {
                int t = f >> 4, d4 = (f & 15) << 2;
                cpa16(kvS + (unsigned)(t*68 + d4) * 4,
                      Vbase + (size_t)(t0 + t)*DHc + d4);
            }
            cpa_commit();
            float* ps = rp;
#pragma unroll
            for (int c = 0; c < 4; c++) {
                float4 pv = make_float4(acc[0][c], acc[1][c], acc[2][c], acc[3][c]);
                *(float4*)(ps + (tx*4 + c)*68 + ty*4) = pv;
            }
            cpa_wait0();
            __syncthreads();   // (d)

            // O += P @ V  (f32x2, pairs along DH cols)
#pragma unroll 8
            for (int t = 0; t < 64; t++) {
                ulonglong2 vv2 = *(ulonglong2*)(kv + t*68 + tx*4);
                float4 p4 = *(float4*)(ps + t*68 + ty*4);
                u64 pa0 = dup2(p4.x), pa1 = dup2(p4.y), pa2v = dup2(p4.z), pa3 = dup2(p4.w);
                oacc2[0][0] = ffma2(pa0,  vv2.x, oacc2[0][0]);
                oacc2[0][1] = ffma2(pa0,  vv2.y, oacc2[0][1]);
                oacc2[1][0] = ffma2(pa1,  vv2.x, oacc2[1][0]);
                oacc2[1][1] = ffma2(pa1,  vv2.y, oacc2[1][1]);
                oacc2[2][0] = ffma2(pa2v, vv2.x, oacc2[2][0]);
                oacc2[2][1] = ffma2(pa2v, vv2.y, oacc2[2][1]);
                oacc2[3][0] = ffma2(pa3,  vv2.x, oacc2[3][0]);
                oacc2[3][1] = ffma2(pa3,  vv2.y, oacc2[3][1]);
            }
        }

        if (!split) {
            // direct TRANSPOSED epilogue: g_CT[h*64+dc][b*1024 + j]
            const int b = bh >> 3;
            float o[4][4];
#pragma unroll
            for (int i = 0; i < 4; i++) {
                float inv = 1.f / lrow[i];
                float2 u0 = unpk2(oacc2[i][0]), u1 = unpk2(oacc2[i][1]);
                o[i][0] = u0.x*inv; o[i][1] = u0.y*inv;
                o[i][2] = u1.x*inv; o[i][3] = u1.y*inv;
            }
#pragma unroll
            for (int c = 0; c < 4; c++) {
                float4 v = make_float4(o[0][c], o[1][c], o[2][c], o[3][c]);
                *(float4*)&g_CT[(size_t)(h*DHc + tx*4 + c) * Mt + b*Sc + j0 + ty*4] = v;
            }
        } else {
            float* P = g_part + (size_t)(((bh*8 + (jt - 8)) << 1) + ci) * 64 * 68;
#pragma unroll
            for (int i = 0; i < 4; i++) {
                const int r = ty*4 + i;
                float2 u0 = unpk2(oacc2[i][0]), u1 = unpk2(oacc2[i][1]);
                *(float4*)&P[r*68 + tx*4] = make_float4(u0.x, u0.y, u1.x, u1.y);
                if (tx == 0) {
                    P[r*68 + 64] = mrow[i];
                    P[r*68 + 65] = lrow[i];
                }
            }
        }
    }
}

// ============================================================
// Combine split-K partials straight into g_CT (transposed).
// ============================================================
__global__ __launch_bounds__(256) void attn_combine() {
    __shared__ float sfA[64], sfB[64];
    const int bh = blockIdx.x >> 3;
    const int jt = 8 + (blockIdx.x & 7);
    const int j0 = jt << 6;
    const int b = bh >> 3, h = bh & 7;

    const float* PA = g_part + (size_t)(((bh*8 + (jt - 8)) << 1) + 0) * 64 * 68;
    const float* PB = g_part + (size_t)(((bh*8 + (jt - 8)) << 1) + 1) * 64 * 68;

    if (threadIdx.x < 64) {
        const int r = threadIdx.x;
        const float mA = PA[r*68 + 64], lA = PA[r*68 + 65];
        const float mB = PB[r*68 + 64], lB = PB[r*68 + 65];
        const float m  = fmaxf(mA, mB);
        const float wA = __expf(mA - m), wB = __expf(mB - m);
        const float inv = 1.f / (wA*lA + wB*lB);
        sfA[r] = wA * inv; sfB[r] = wB * inv;
    }
    __syncthreads();

    const int c  = threadIdx.x & 63;      // dc row of g_CT
    const int jg = threadIdx.x >> 6;      // 0..3 (16 j each)

    float buf[16];
#pragma unroll
    for (int u = 0; u < 16; u++) {
        const int r = jg*16 + u;
        buf[u] = sfA[r] * PA[r*68 + c] + sfB[r] * PB[r*68 + c];
    }
    float* dst = &g_CT[(size_t)(h*DHc + c) * Mt + b*Sc + j0 + jg*16];
#pragma unroll
    for (int u = 0; u < 16; u += 4)
        *(float4*)&dst[u] = make_float4(buf[u], buf[u+1], buf[u+2], buf[u+3]);
}

// ============================================================
extern "C" void kernel_launch(void* const* d_in, const int* in_sizes, int n_in,
                              void* d_out, int out_size) {
    (void)in_sizes; (void)n_in; (void)out_size;
    const float* queries = (const float*)d_in[0];
    const float* keysp   = (const float*)d_in[1];
    const float* valuesp = (const float*)d_in[2];
    // d_in[3] = mask (causal; applied analytically)
    const float* Wq  = (const float*)d_in[4];
    const float* Wk  = (const float*)d_in[5];
    const float* Wv  = (const float*)d_in[6];
    const float* Wo  = (const float*)d_in[7];
    const float* rel = (const float*)d_in[8];
    float* out = (float*)d_out;

    float *pQ, *pK, *pV;
    cudaGetSymbolAddress((void**)&pQ, g_Q);
    cudaGetSymbolAddress((void**)&pK, g_K);
    cudaGetSymbolAddress((void**)&pV, g_V);

    // 1) transpose activations -> g_AT (also resets attn work queue)
    transpose3<<<dim3(Dc/32, Mt/32, 3), 256>>>(queries, keysp, valuesp);

    // 2) fused QKV projections (cp.async pipelined GEMM)
    proj3<<<dim3(Dc/64, Mt/128, 3), 256>>>(Wq, Wk, Wv, pQ, pK, pV);

    // 3) attention: persistent work-stealing workers (152 SM * 3)
    const int smem = (2*64*68 + 64*128 + 4) * (int)sizeof(float);
    cudaFuncSetAttribute(attn_kernel, cudaFuncAttributeMaxDynamicSharedMemorySize, smem);
    attn_kernel<<<456, 256, smem>>>(rel);

    // 3b) merge partials for split j-tiles -> g_CT
    attn_combine<<<Bc*Hc*8, 256>>>();

    // 4) output projection reads g_CT directly (transpose1 eliminated)
    gemm_out<<<dim3(Dc/64, Mt/128), 256>>>(Wo, out);
}